// round 12
// baseline (speedup 1.0000x reference)
#include <cuda_runtime.h>
#include <cuda_bf16.h>
#include <cstdint>
#include <cstddef>

// Problem constants
#define NB 4
#define NC 64
#define NL 1024
#define HS 63
#define NP 3969
#define CSTR 3972
#define FPW 68

// GEMM tiling: CTA 128x256, 16 warps (2M x 8N), warp tile 64x32
#define KT 16
#define MT 8
#define PT 16
#define A_TILE_B  (128 * 64 * 2)      // 16384
#define F_TILE_B  (256 * 64 * 2)      // 32768
#define STAGE_B   (2 * A_TILE_B + 2 * F_TILE_B)   // 98304
#define NSTG 2
#define SMEM_TOTAL (NSTG * STAGE_B)               // 196608
#define GT 512

// -------- scratch globals --------
__device__ float g_inv[NB * NC];
__device__ float g_fpad[(size_t)NB * NC * 66 * FPW];
__device__ float g_cos[(size_t)NB * NL * CSTR];
__device__ float g_w[(size_t)NB * NL * CSTR];
__device__ float g_mmk[NB * NL];
__device__ float g_mmp[NB * NP];
__device__ __align__(128) unsigned char g_Abf[(size_t)NB * KT * MT * 2 * A_TILE_B];  // 16 MB
__device__ __align__(128) unsigned char g_Fbf[(size_t)NB * KT * PT * 2 * F_TILE_B];  // 64 MB

__device__ __forceinline__ int clampi(int v, int lo, int hi) {
    return v < lo ? lo : (v > hi ? hi : v);
}
__device__ __forceinline__ uint32_t smem_u32(const void* p) {
    uint32_t a;
    asm("{ .reg .u64 t; cvta.to.shared.u64 t, %1; cvt.u32.u64 %0, t; }" : "=r"(a) : "l"(p));
    return a;
}
__device__ __forceinline__ void cp16(uint32_t sdst, const void* gsrc) {
    asm volatile("cp.async.cg.shared.global [%0], [%1], 16;" :: "r"(sdst), "l"(gsrc) : "memory");
}
__device__ __forceinline__ void cp_commit() {
    asm volatile("cp.async.commit_group;" ::: "memory");
}
template <int N>
__device__ __forceinline__ void cp_wait() {
    asm volatile("cp.async.wait_group %0;" :: "n"(N) : "memory");
}
__device__ __forceinline__ void ldm_x4(uint32_t* r, uint32_t addr) {
    asm volatile("ldmatrix.sync.aligned.m8n8.x4.shared.b16 {%0,%1,%2,%3}, [%4];"
                 : "=r"(r[0]), "=r"(r[1]), "=r"(r[2]), "=r"(r[3]) : "r"(addr));
}
__device__ __forceinline__ void mma16816(float* d, const uint32_t* a, uint32_t b0, uint32_t b1) {
    asm volatile(
        "mma.sync.aligned.m16n8k16.row.col.f32.bf16.bf16.f32 "
        "{%0,%1,%2,%3}, {%4,%5,%6,%7}, {%8,%9}, {%0,%1,%2,%3};"
        : "+f"(d[0]), "+f"(d[1]), "+f"(d[2]), "+f"(d[3])
        : "r"(a[0]), "r"(a[1]), "r"(a[2]), "r"(a[3]), "r"(b0), "r"(b1));
}

// -------- edge-padded f --------
__global__ void k_buildF(const float* __restrict__ f) {
    int idx = blockIdx.x * 256 + threadIdx.x;
    if (idx >= NB * NC * 66 * FPW) return;
    int col = idx % FPW;
    int row = (idx / FPW) % 66;
    int bc  = idx / (FPW * 66);
    float v = 0.f;
    if (col < 66) {
        int r = clampi(row - 1, 0, 63), c2 = clampi(col - 1, 0, 63);
        v = f[(size_t)bc * 4096 + r * 64 + c2];
    }
    g_fpad[idx] = v;
}

// -------- per-(b,c) L2 norm --------
__global__ void k_norm(const float* __restrict__ bin) {
    int bc = blockIdx.x;
    const float* p = bin + (size_t)bc * 4096;
    float s = 0.f;
    for (int i = threadIdx.x; i < 4096; i += 256) { float v = p[i]; s += v * v; }
    __shared__ float sm[256];
    sm[threadIdx.x] = s; __syncthreads();
    for (int o = 128; o > 0; o >>= 1) {
        if (threadIdx.x < o) sm[threadIdx.x] += sm[threadIdx.x + o];
        __syncthreads();
    }
    if (threadIdx.x == 0) g_inv[bc] = rsqrtf(sm[0] + 1e-8f);
}

// -------- merged A+F bf16 tile build (pre-swizzled, hi/lo) --------
#define A_BLKS 2048
__global__ void k_buildAFbf(const float* __restrict__ bin) {
    if (blockIdx.x < A_BLKS) {
        int idx = blockIdx.x * 256 + threadIdx.x;
        int kc8 = idx & 7;
        int row = (idx >> 3) & 127;
        int lt  = (idx >> 10) & 7;
        int kt  = (idx >> 13) & 15;
        int b   = idx >> 17;
        int l = lt * 128 + row, lh = l >> 5, lw = l & 31;
        union { __nv_bfloat16 h[8]; uint4 v; } Hi, Lo;
#pragma unroll
        for (int r = 0; r < 8; r++) {
            int k = kt * 64 + kc8 * 8 + r;
            int c = k >> 4, i = (k >> 2) & 3, j = k & 3;
            int rr = clampi(2 * lh + i - 1, 0, 63);
            int cc = clampi(2 * lw + j - 1, 0, 63);
            float v = bin[(((size_t)(b * NC + c)) << 12) + (rr << 6) + cc] * g_inv[b * NC + c];
            __nv_bfloat16 hi = __float2bfloat16(v);
            Hi.h[r] = hi;
            Lo.h[r] = __float2bfloat16(v - __bfloat162float(hi));
        }
        uint32_t cb = row * 128 + kc8 * 16;
        uint32_t sw = cb ^ ((cb >> 3) & 0x70);
        size_t base = ((size_t)((b * KT + kt) * MT + lt)) * (2 * A_TILE_B);
        *(uint4*)(g_Abf + base + sw) = Hi.v;
        *(uint4*)(g_Abf + base + A_TILE_B + sw) = Lo.v;
    } else {
        int idx = (blockIdx.x - A_BLKS) * 256 + threadIdx.x;   // 2^21 total
        int kc8 = idx & 7;
        int row = (idx >> 3) & 255;
        int pt  = (idx >> 11) & 15;
        int kt  = (idx >> 15) & 15;
        int b   = idx >> 19;
        int p = pt * 256 + row;
        union { __nv_bfloat16 h[8]; uint4 v; } Hi, Lo;
        if (p < NP) {
            int y = p / HS, x = p - y * HS;
#pragma unroll
            for (int r = 0; r < 8; r++) {
                int k = kt * 64 + kc8 * 8 + r;
                int c = k >> 4, i = (k >> 2) & 3, j = k & 3;
                float v = g_fpad[((size_t)(b * NC + c) * 66 + (y + i)) * FPW + (x + j)];
                __nv_bfloat16 hi = __float2bfloat16(v);
                Hi.h[r] = hi;
                Lo.h[r] = __float2bfloat16(v - __bfloat162float(hi));
            }
        } else {
            Hi.v = make_uint4(0, 0, 0, 0);
            Lo.v = make_uint4(0, 0, 0, 0);
        }
        uint32_t cb = row * 128 + kc8 * 16;
        uint32_t sw = cb ^ ((cb >> 3) & 0x70);
        size_t base = ((size_t)((b * KT + kt) * PT + pt)) * (2 * F_TILE_B);
        *(uint4*)(g_Fbf + base + sw) = Hi.v;
        *(uint4*)(g_Fbf + base + F_TILE_B + sw) = Lo.v;
    }
}

// -------- mma.sync GEMM: 512 thr, 16 warps (2Mx8N), warp tile 64x32 --------
__global__ __launch_bounds__(GT, 1) void k_gemm_mma() {
    extern __shared__ __align__(1024) unsigned char smem[];
    uint32_t sb = smem_u32(smem);
    int tid = threadIdx.x;
    int wid = tid >> 5, lane = tid & 31;
    int pt = blockIdx.x, lt = blockIdx.y, b = blockIdx.z;

    int warpM = (wid >> 3) * 64;         // 2 M groups
    int warpN = (wid & 7) * 32;          // 8 N groups

    int a_row = lane & 15;
    int a_kh  = lane >> 4;
    int b_row = (lane & 7) | (((lane >> 4) & 1) << 3);
    int b_kh  = (lane >> 3) & 1;

    float acc[4][4][4];
#pragma unroll
    for (int mt = 0; mt < 4; mt++)
#pragma unroll
        for (int nt = 0; nt < 4; nt++)
#pragma unroll
            for (int r = 0; r < 4; r++) acc[mt][nt][r] = 0.f;

    const size_t Astride = (size_t)MT * 2 * A_TILE_B;
    const size_t Fstride = (size_t)PT * 2 * F_TILE_B;
    const unsigned char* Ab0 = g_Abf + ((size_t)(b * KT) * MT + lt) * (2 * A_TILE_B);
    const unsigned char* Fb0 = g_Fbf + ((size_t)(b * KT) * PT + pt) * (2 * F_TILE_B);

    auto load_stage = [&](int s, int kt) {
        uint32_t dst = sb + s * STAGE_B;
        const unsigned char* As = Ab0 + (size_t)kt * Astride;
        const unsigned char* Fs = Fb0 + (size_t)kt * Fstride;
#pragma unroll
        for (int i = 0; i < 12; i++) {
            int idx = tid + i * GT;                 // 0..6143 chunks of 16B
            const unsigned char* g = (idx < 2048) ? (As + (size_t)idx * 16)
                                                  : (Fs + (size_t)(idx - 2048) * 16);
            cp16(dst + idx * 16, g);
        }
        cp_commit();
    };

    load_stage(0, 0);

    for (int kt = 0; kt < KT; kt++) {
        int s = kt & 1;
        if (kt + 1 < KT) { load_stage(s ^ 1, kt + 1); cp_wait<1>(); }
        else             { cp_wait<0>(); }
        __syncthreads();

        uint32_t SA = sb + s * STAGE_B;
#pragma unroll
        for (int ks = 0; ks < 4; ks++) {
            uint32_t ahi[4][4], alo[4][4], fbuf[2][4];
#pragma unroll
            for (int mt = 0; mt < 4; mt++) {
                int row = warpM + mt * 16 + a_row;
                uint32_t ad = SA + row * 128 + (((ks * 2 + a_kh) ^ (a_row & 7)) << 4);
                ldm_x4(ahi[mt], ad);
                ldm_x4(alo[mt], ad + A_TILE_B);
            }
            // F hi fragments
#pragma unroll
            for (int ntp = 0; ntp < 2; ntp++) {
                int row = warpN + ntp * 16 + b_row;
                uint32_t fd = SA + 2 * A_TILE_B + row * 128 + (((ks * 2 + b_kh) ^ (b_row & 7)) << 4);
                ldm_x4(fbuf[ntp], fd);
            }
            // terms using F_hi: hi*hi then lo*hi (fbuf stays live, then dies)
#pragma unroll
            for (int mt = 0; mt < 4; mt++)
#pragma unroll
                for (int nt = 0; nt < 4; nt++) {
                    int ntp = nt >> 1, rb = (nt & 1) * 2;
                    mma16816(acc[mt][nt], ahi[mt], fbuf[ntp][rb], fbuf[ntp][rb + 1]);
                }
#pragma unroll
            for (int mt = 0; mt < 4; mt++)
#pragma unroll
                for (int nt = 0; nt < 4; nt++) {
                    int ntp = nt >> 1, rb = (nt & 1) * 2;
                    mma16816(acc[mt][nt], alo[mt], fbuf[ntp][rb], fbuf[ntp][rb + 1]);
                }
            // reload fbuf with F_lo, term hi*lo
#pragma unroll
            for (int ntp = 0; ntp < 2; ntp++) {
                int row = warpN + ntp * 16 + b_row;
                uint32_t fd = SA + 2 * A_TILE_B + F_TILE_B + row * 128 + (((ks * 2 + b_kh) ^ (b_row & 7)) << 4);
                ldm_x4(fbuf[ntp], fd);
            }
#pragma unroll
            for (int mt = 0; mt < 4; mt++)
#pragma unroll
                for (int nt = 0; nt < 4; nt++) {
                    int ntp = nt >> 1, rb = (nt & 1) * 2;
                    mma16816(acc[mt][nt], ahi[mt], fbuf[ntp][rb], fbuf[ntp][rb + 1]);
                }
        }
        __syncthreads();
    }

    // epilogue (CSTR stride)
    int lrow = lt * 128 + warpM + (lane >> 2);
    int pcol = pt * 256 + warpN + (lane & 3) * 2;
#pragma unroll
    for (int mt = 0; mt < 4; mt++) {
        int l0 = lrow + mt * 16;
        float* C0 = g_cos + ((size_t)(b * NL + l0)) * CSTR;
        float* C8 = C0 + (size_t)8 * CSTR;
#pragma unroll
        for (int nt = 0; nt < 4; nt++) {
            int p = pcol + nt * 8;
            if (p < NP)     { C0[p]     = acc[mt][nt][0]; C8[p]     = acc[mt][nt][2]; }
            if (p + 1 < NP) { C0[p + 1] = acc[mt][nt][1]; C8[p + 1] = acc[mt][nt][3]; }
        }
    }
}

// -------- first diagonal pass (vectorized, CSTR) --------
#define NP4 993
__global__ __launch_bounds__(256) void k_diag1() {
    int gp = blockIdx.x * 256 + threadIdx.x;
    int v4 = gp % NP4;
    int l  = (gp / NP4) & 1023;
    int bb = gp / (NP4 * 1024);
    if (bb >= NB) return;
    int p4 = v4 * 4;
    const float* cb = g_cos + (size_t)bb * NL * CSTR;
    const float4 z4 = make_float4(0.f, 0.f, 0.f, 0.f);
    float4 cm = (l > 0)      ? *(const float4*)(cb + (size_t)(l - 1) * CSTR + p4) : z4;
    float4 cc =                *(const float4*)(cb + (size_t)l * CSTR + p4);
    float4 cp = (l < NL - 1) ? *(const float4*)(cb + (size_t)(l + 1) * CSTR + p4) : z4;
    float cmw = (l > 0 && p4 > 0) ? cb[(size_t)(l - 1) * CSTR + p4 - 1] : 0.f;
    float cpn = (l < NL - 1 && p4 + 4 < NP) ? cb[(size_t)(l + 1) * CSTR + p4 + 4] : 0.f;
    float cpy = (p4 + 1 < NP) ? cp.y : 0.f;
    float cpz = (p4 + 2 < NP) ? cp.z : 0.f;
    float cpw = (p4 + 3 < NP) ? cp.w : 0.f;
    float4 w;
    w.x = cmw  + cc.x + cpy;
    w.y = cm.x + cc.y + cpz;
    w.z = cm.y + cc.z + cpw;
    w.w = cm.z + cc.w + cpn;
    *(float4*)(g_w + (size_t)bb * NL * CSTR + (size_t)l * CSTR + p4) = w;
}

// -------- mask means (merged) --------
__global__ void k_masks(const float* __restrict__ mask) {
    int idx = blockIdx.x * 256 + threadIdx.x;
    if (idx < NB * NL) {
        int bb = idx >> 10, l = idx & 1023;
        int lh = l >> 5, lw = l & 31;
        float s = 0.f;
        for (int i = 0; i < 4; i++)
            for (int j = 0; j < 4; j++) {
                int r  = clampi(2 * lh + i - 1, 0, 63);
                int cc = clampi(2 * lw + j - 1, 0, 63);
                s += 1.0f - mask[bb * 4096 + r * 64 + cc];
            }
        g_mmk[idx] = s * 0.0625f;
    } else {
        int id2 = idx - NB * NL;
        if (id2 >= NB * NP) return;
        int bb = id2 / NP;
        int p  = id2 - bb * NP;
        int y  = p / HS, x = p - y * HS;
        float s = 0.f;
        for (int i = 0; i < 4; i++)
            for (int j = 0; j < 4; j++) {
                int r  = clampi(y + i - 1, 0, 63);
                int cc = clampi(x + j - 1, 0, 63);
                s += 1.0f - mask[bb * 4096 + r * 64 + cc];
            }
        g_mmp[id2] = s * 0.0625f;
    }
}

// -------- fused value: 3-point gather on w --------
__device__ __forceinline__ float fused_val(const float* __restrict__ wb, int bb, int l,
                                           const int mpr[3], const bool mval[3],
                                           float mmpv) {
    int lh = l >> 5, lw = l & 31;
    int n2 = lw * 32 + lh;
    float fs = 0.f;
#pragma unroll
    for (int d2 = 0; d2 < 3; d2++) {
        int n2d = n2 + d2 - 1;
        if ((unsigned)n2d < 1024u && mval[d2]) {
            int np = ((n2d & 31) << 5) | (n2d >> 5);
            fs += wb[(size_t)np * CSTR + mpr[d2]];
        }
    }
    float mmkv = g_mmk[bb * NL + l];
    float mmf = (((mmkv > mmpv) && (mmpv > 0.5f)) || (mmkv == 1.0f)) ? 1.f : 0.f;
    return fs * mmf * 10.0f;
}

// -------- single-kernel fuse + softmax --------
__global__ __launch_bounds__(256) void k_fuse(float* __restrict__ out) {
    int bb = blockIdx.y;
    int p0 = blockIdx.x * 32;
    int tid = threadIdx.x;
    int w = tid >> 5, lane = tid & 31;
    int p = p0 + lane;
    bool vp = p < NP;
    int pp = vp ? p : 0;

    int y = pp / HS, x = pp - y * HS;
    int m2 = x * HS + y;
    int mpr[3]; bool mval[3];
#pragma unroll
    for (int d = 0; d < 3; d++) {
        int m2d = m2 + d - 1;
        mval[d] = (m2d >= 0 && m2d < NP);
        int mm2 = mval[d] ? m2d : 0;
        int xp2 = mm2 / HS, yp2 = mm2 - xp2 * HS;
        mpr[d] = yp2 * HS + xp2;
    }

    const float* wb = g_w + (size_t)bb * NL * CSTR;
    float mmpv = g_mmp[bb * NP + pp];

    int lbeg = w * 128, lend = lbeg + 128;
    float mx = -INFINITY, s = 0.f;
    float* ob = out + (size_t)bb * NL * NP + pp;
    for (int l = lbeg; l < lend; l++) {
        float v = fused_val(wb, bb, l, mpr, mval, mmpv);
        if (vp) ob[(size_t)l * NP] = v;
        float mn = fmaxf(mx, v);
        s = s * __expf(mx - mn) + __expf(v - mn);
        mx = mn;
    }

    __shared__ float smM[8][32], smS[8][32];
    __shared__ float fM[32], fIS[32];
    smM[w][lane] = mx; smS[w][lane] = s;
    __syncthreads();
    if (tid < 32) {
        float M = -INFINITY;
#pragma unroll
        for (int ww = 0; ww < 8; ww++) M = fmaxf(M, smM[ww][tid]);
        float S = 0.f;
#pragma unroll
        for (int ww = 0; ww < 8; ww++) S += smS[ww][tid] * __expf(smM[ww][tid] - M);
        fM[tid] = M; fIS[tid] = 1.0f / S;
    }
    __syncthreads();
    float M = fM[lane], IS = fIS[lane];

    if (vp)
        for (int l = lbeg; l < lend; l++) {
            size_t o = (size_t)l * NP;
            ob[o] = __expf(ob[o] - M) * IS;
        }
}

// -------- launch --------
extern "C" void kernel_launch(void* const* d_in, const int* in_sizes, int n_in,
                              void* d_out, int out_size) {
    const float* f    = (const float*)d_in[0];
    const float* b    = (const float*)d_in[1];
    const float* mask = (const float*)d_in[2];
    float* out = (float*)d_out;

    static int smem_set = 0;
    if (!smem_set) {
        cudaFuncSetAttribute(k_gemm_mma, cudaFuncAttributeMaxDynamicSharedMemorySize, SMEM_TOTAL);
        smem_set = 1;
    }

    k_buildF<<<(NB * NC * 66 * FPW + 255) / 256, 256>>>(f);                // 1
    k_norm<<<NB * NC, 256>>>(b);                                           // 2
    k_buildAFbf<<<A_BLKS + 8192, 256>>>(b);                                // 3
    k_gemm_mma<<<dim3(PT, MT, NB), GT, SMEM_TOTAL>>>();                    // 4  <- ncu window
    k_diag1<<<(NB * 1024 * NP4 + 255) / 256, 256>>>();                     // 5
    k_masks<<<(NB * NL + NB * NP + 255) / 256, 256>>>(mask);               // 6
    k_fuse<<<dim3((NP + 31) / 32, NB), 256>>>(out);                        // 7
}

// round 13
// speedup vs baseline: 1.4749x; 1.4749x over previous
#include <cuda_runtime.h>
#include <cuda_bf16.h>
#include <cstdint>
#include <cstddef>

// Problem constants
#define NB 4
#define NC 64
#define NL 1024
#define HS 63
#define NP 3969
#define CSTR 3972
#define FPW 68

// GEMM tiling (R11 config: CTA 128x128, 8 warps 2Mx4N, warp tile 64x32)
#define KT 16
#define MT 8
#define PT 32
#define A_TILE_B  (128 * 64 * 2)
#define F_TILE_B  (128 * 64 * 2)
#define STAGE_B   (2 * A_TILE_B + 2 * F_TILE_B)   // 65536
#define NSTG 3
#define SMEM_TOTAL (NSTG * STAGE_B)               // 196608

// -------- scratch globals --------
__device__ float g_inv[NB * NC];
__device__ float g_fpad[(size_t)NB * NC * 66 * FPW];
__device__ float g_cos[(size_t)NB * NL * CSTR];
__device__ float g_w[(size_t)NB * NL * CSTR];
__device__ float g_mmk[NB * NL];
__device__ float g_mmp[NB * NP];
__device__ __align__(128) unsigned char g_Abf[(size_t)NB * KT * MT * 2 * A_TILE_B];
__device__ __align__(128) unsigned char g_Fbf[(size_t)NB * KT * PT * 2 * F_TILE_B];

__device__ __forceinline__ int clampi(int v, int lo, int hi) {
    return v < lo ? lo : (v > hi ? hi : v);
}
__device__ __forceinline__ uint32_t smem_u32(const void* p) {
    uint32_t a;
    asm("{ .reg .u64 t; cvta.to.shared.u64 t, %1; cvt.u32.u64 %0, t; }" : "=r"(a) : "l"(p));
    return a;
}
__device__ __forceinline__ void cp16(uint32_t sdst, const void* gsrc) {
    asm volatile("cp.async.cg.shared.global [%0], [%1], 16;" :: "r"(sdst), "l"(gsrc) : "memory");
}
__device__ __forceinline__ void cp_commit() {
    asm volatile("cp.async.commit_group;" ::: "memory");
}
template <int N>
__device__ __forceinline__ void cp_wait() {
    asm volatile("cp.async.wait_group %0;" :: "n"(N) : "memory");
}
__device__ __forceinline__ void ldm_x4(uint32_t* r, uint32_t addr) {
    asm volatile("ldmatrix.sync.aligned.m8n8.x4.shared.b16 {%0,%1,%2,%3}, [%4];"
                 : "=r"(r[0]), "=r"(r[1]), "=r"(r[2]), "=r"(r[3]) : "r"(addr));
}
__device__ __forceinline__ void mma16816(float* d, const uint32_t* a, uint32_t b0, uint32_t b1) {
    asm volatile(
        "mma.sync.aligned.m16n8k16.row.col.f32.bf16.bf16.f32 "
        "{%0,%1,%2,%3}, {%4,%5,%6,%7}, {%8,%9}, {%0,%1,%2,%3};"
        : "+f"(d[0]), "+f"(d[1]), "+f"(d[2]), "+f"(d[3])
        : "r"(a[0]), "r"(a[1]), "r"(a[2]), "r"(a[3]), "r"(b0), "r"(b1));
}

// -------- launch 1: edge-padded f + per-(b,c) L2 norm (merged) --------
#define BF_BLKS ((NB * NC * 66 * FPW + 255) / 256)   // 4488
__global__ void k_prep(const float* __restrict__ f, const float* __restrict__ bin) {
    if (blockIdx.x < BF_BLKS) {
        int idx = blockIdx.x * 256 + threadIdx.x;
        if (idx >= NB * NC * 66 * FPW) return;
        int col = idx % FPW;
        int row = (idx / FPW) % 66;
        int bc  = idx / (FPW * 66);
        float v = 0.f;
        if (col < 66) {
            int r = clampi(row - 1, 0, 63), c2 = clampi(col - 1, 0, 63);
            v = f[(size_t)bc * 4096 + r * 64 + c2];
        }
        g_fpad[idx] = v;
    } else {
        int bc = blockIdx.x - BF_BLKS;          // 0..255
        const float* p = bin + (size_t)bc * 4096;
        float s = 0.f;
        for (int i = threadIdx.x; i < 4096; i += 256) { float v = p[i]; s += v * v; }
        __shared__ float sm[256];
        sm[threadIdx.x] = s; __syncthreads();
        for (int o = 128; o > 0; o >>= 1) {
            if (threadIdx.x < o) sm[threadIdx.x] += sm[threadIdx.x + o];
            __syncthreads();
        }
        if (threadIdx.x == 0) g_inv[bc] = rsqrtf(sm[0] + 1e-8f);
    }
}

// -------- launch 2: A+F bf16 tile build (pre-swizzled, hi/lo) + mask means --------
#define A_BLKS 2048
#define F_BLKS 8192
#define MK_BLKS ((NB * NL + NB * NP + 255) / 256)    // 78
__global__ void k_buildAFbf(const float* __restrict__ bin, const float* __restrict__ mask) {
    if (blockIdx.x < A_BLKS) {
        int idx = blockIdx.x * 256 + threadIdx.x;
        int kc8 = idx & 7;
        int row = (idx >> 3) & 127;
        int lt  = (idx >> 10) & 7;
        int kt  = (idx >> 13) & 15;
        int b   = idx >> 17;
        int l = lt * 128 + row, lh = l >> 5, lw = l & 31;
        union { __nv_bfloat16 h[8]; uint4 v; } Hi, Lo;
#pragma unroll
        for (int r = 0; r < 8; r++) {
            int k = kt * 64 + kc8 * 8 + r;
            int c = k >> 4, i = (k >> 2) & 3, j = k & 3;
            int rr = clampi(2 * lh + i - 1, 0, 63);
            int cc = clampi(2 * lw + j - 1, 0, 63);
            float v = bin[(((size_t)(b * NC + c)) << 12) + (rr << 6) + cc] * g_inv[b * NC + c];
            __nv_bfloat16 hi = __float2bfloat16(v);
            Hi.h[r] = hi;
            Lo.h[r] = __float2bfloat16(v - __bfloat162float(hi));
        }
        uint32_t cb = row * 128 + kc8 * 16;
        uint32_t sw = cb ^ ((cb >> 3) & 0x70);
        size_t base = ((size_t)((b * KT + kt) * MT + lt)) * (2 * A_TILE_B);
        *(uint4*)(g_Abf + base + sw) = Hi.v;
        *(uint4*)(g_Abf + base + A_TILE_B + sw) = Lo.v;
    } else if (blockIdx.x < A_BLKS + F_BLKS) {
        int idx = (blockIdx.x - A_BLKS) * 256 + threadIdx.x;
        int kc8 = idx & 7;
        int row = (idx >> 3) & 127;
        int pt  = (idx >> 10) & 31;
        int kt  = (idx >> 15) & 15;
        int b   = idx >> 19;
        int p = pt * 128 + row;
        union { __nv_bfloat16 h[8]; uint4 v; } Hi, Lo;
        if (p < NP) {
            int y = p / HS, x = p - y * HS;
#pragma unroll
            for (int r = 0; r < 8; r++) {
                int k = kt * 64 + kc8 * 8 + r;
                int c = k >> 4, i = (k >> 2) & 3, j = k & 3;
                float v = g_fpad[((size_t)(b * NC + c) * 66 + (y + i)) * FPW + (x + j)];
                __nv_bfloat16 hi = __float2bfloat16(v);
                Hi.h[r] = hi;
                Lo.h[r] = __float2bfloat16(v - __bfloat162float(hi));
            }
        } else {
            Hi.v = make_uint4(0, 0, 0, 0);
            Lo.v = make_uint4(0, 0, 0, 0);
        }
        uint32_t cb = row * 128 + kc8 * 16;
        uint32_t sw = cb ^ ((cb >> 3) & 0x70);
        size_t base = ((size_t)((b * KT + kt) * PT + pt)) * (2 * F_TILE_B);
        *(uint4*)(g_Fbf + base + sw) = Hi.v;
        *(uint4*)(g_Fbf + base + F_TILE_B + sw) = Lo.v;
    } else {
        int idx = (blockIdx.x - A_BLKS - F_BLKS) * 256 + threadIdx.x;
        if (idx < NB * NL) {
            int bb = idx >> 10, l = idx & 1023;
            int lh = l >> 5, lw = l & 31;
            float s = 0.f;
            for (int i = 0; i < 4; i++)
                for (int j = 0; j < 4; j++) {
                    int r  = clampi(2 * lh + i - 1, 0, 63);
                    int cc = clampi(2 * lw + j - 1, 0, 63);
                    s += 1.0f - mask[bb * 4096 + r * 64 + cc];
                }
            g_mmk[idx] = s * 0.0625f;
        } else {
            int id2 = idx - NB * NL;
            if (id2 >= NB * NP) return;
            int bb = id2 / NP;
            int p  = id2 - bb * NP;
            int y  = p / HS, x = p - y * HS;
            float s = 0.f;
            for (int i = 0; i < 4; i++)
                for (int j = 0; j < 4; j++) {
                    int r  = clampi(y + i - 1, 0, 63);
                    int cc = clampi(x + j - 1, 0, 63);
                    s += 1.0f - mask[bb * 4096 + r * 64 + cc];
                }
            g_mmp[id2] = s * 0.0625f;
        }
    }
}

// -------- launch 3: mma.sync GEMM (exact R11: 8 warps, frag double-buffer) --------
__global__ __launch_bounds__(256, 1) void k_gemm_mma() {
    extern __shared__ __align__(1024) unsigned char smem[];
    uint32_t sb = smem_u32(smem);
    int tid = threadIdx.x;
    int wid = tid >> 5, lane = tid & 31;
    int pt = blockIdx.x, lt = blockIdx.y, b = blockIdx.z;

    int warpM = (wid >> 2) * 64;
    int warpN = (wid & 3) * 32;

    int a_row = lane & 15;
    int a_kh  = lane >> 4;
    int b_row = (lane & 7) | (((lane >> 4) & 1) << 3);
    int b_kh  = (lane >> 3) & 1;

    float acc[4][4][4];
#pragma unroll
    for (int mt = 0; mt < 4; mt++)
#pragma unroll
        for (int nt = 0; nt < 4; nt++)
#pragma unroll
            for (int r = 0; r < 4; r++) acc[mt][nt][r] = 0.f;

    const size_t Astride = (size_t)MT * 2 * A_TILE_B;
    const size_t Fstride = (size_t)PT * 2 * F_TILE_B;
    const unsigned char* Ab0 = g_Abf + ((size_t)(b * KT) * MT + lt) * (2 * A_TILE_B);
    const unsigned char* Fb0 = g_Fbf + ((size_t)(b * KT) * PT + pt) * (2 * F_TILE_B);

    auto load_stage = [&](int s, int kt) {
        uint32_t dst = sb + s * STAGE_B;
        const unsigned char* As = Ab0 + (size_t)kt * Astride;
        const unsigned char* Fs = Fb0 + (size_t)kt * Fstride;
#pragma unroll
        for (int i = 0; i < 16; i++) {
            int idx = tid + i * 256;
            const unsigned char* g = (idx < 2048) ? (As + (size_t)idx * 16)
                                                  : (Fs + (size_t)(idx - 2048) * 16);
            cp16(dst + idx * 16, g);
        }
        cp_commit();
    };

    uint32_t ahi[2][4][4], alo[2][4][4], fhi[2][2][4], flo[2][2][4];

    auto load_frags = [&](int buf, uint32_t SA, int ks) {
#pragma unroll
        for (int mt = 0; mt < 4; mt++) {
            int row = warpM + mt * 16 + a_row;
            uint32_t ad = SA + row * 128 + (((ks * 2 + a_kh) ^ (a_row & 7)) << 4);
            ldm_x4(ahi[buf][mt], ad);
            ldm_x4(alo[buf][mt], ad + 16384);
        }
#pragma unroll
        for (int ntp = 0; ntp < 2; ntp++) {
            int row = warpN + ntp * 16 + b_row;
            uint32_t fd = SA + 32768 + row * 128 + (((ks * 2 + b_kh) ^ (b_row & 7)) << 4);
            ldm_x4(fhi[buf][ntp], fd);
            ldm_x4(flo[buf][ntp], fd + 16384);
        }
    };

    load_stage(0, 0);
    load_stage(1, 1);

    for (int kt = 0; kt < KT; kt++) {
        int s = kt % NSTG;
        if (kt + 2 < KT) { load_stage((kt + 2) % NSTG, kt + 2); cp_wait<2>(); }
        else if (kt + 1 < KT) cp_wait<1>();
        else cp_wait<0>();
        __syncthreads();

        uint32_t SA = sb + s * STAGE_B;
        load_frags(0, SA, 0);
#pragma unroll
        for (int ks = 0; ks < 4; ks++) {
            int cur = ks & 1, nxt = cur ^ 1;
            if (ks < 3) load_frags(nxt, SA, ks + 1);
#pragma unroll
            for (int term = 0; term < 3; term++)
#pragma unroll
                for (int mt = 0; mt < 4; mt++)
#pragma unroll
                    for (int nt = 0; nt < 4; nt++) {
                        int ntp = nt >> 1, rb = (nt & 1) * 2;
                        if (term == 0)
                            mma16816(acc[mt][nt], ahi[cur][mt], fhi[cur][ntp][rb], fhi[cur][ntp][rb + 1]);
                        else if (term == 1)
                            mma16816(acc[mt][nt], ahi[cur][mt], flo[cur][ntp][rb], flo[cur][ntp][rb + 1]);
                        else
                            mma16816(acc[mt][nt], alo[cur][mt], fhi[cur][ntp][rb], fhi[cur][ntp][rb + 1]);
                    }
        }
        __syncthreads();
    }

    int lrow = lt * 128 + warpM + (lane >> 2);
    int pcol = pt * 128 + warpN + (lane & 3) * 2;
#pragma unroll
    for (int mt = 0; mt < 4; mt++) {
        int l0 = lrow + mt * 16;
        float* C0 = g_cos + ((size_t)(b * NL + l0)) * CSTR;
        float* C8 = C0 + (size_t)8 * CSTR;
#pragma unroll
        for (int nt = 0; nt < 4; nt++) {
            int p = pcol + nt * 8;
            if (p < NP)     { C0[p]     = acc[mt][nt][0]; C8[p]     = acc[mt][nt][2]; }
            if (p + 1 < NP) { C0[p + 1] = acc[mt][nt][1]; C8[p + 1] = acc[mt][nt][3]; }
        }
    }
}

// -------- launch 4: first diagonal pass (vectorized, CSTR) --------
#define NP4 993
__global__ __launch_bounds__(256) void k_diag1() {
    int gp = blockIdx.x * 256 + threadIdx.x;
    int v4 = gp % NP4;
    int l  = (gp / NP4) & 1023;
    int bb = gp / (NP4 * 1024);
    if (bb >= NB) return;
    int p4 = v4 * 4;
    const float* cb = g_cos + (size_t)bb * NL * CSTR;
    const float4 z4 = make_float4(0.f, 0.f, 0.f, 0.f);
    float4 cm = (l > 0)      ? *(const float4*)(cb + (size_t)(l - 1) * CSTR + p4) : z4;
    float4 cc =                *(const float4*)(cb + (size_t)l * CSTR + p4);
    float4 cp = (l < NL - 1) ? *(const float4*)(cb + (size_t)(l + 1) * CSTR + p4) : z4;
    float cmw = (l > 0 && p4 > 0) ? cb[(size_t)(l - 1) * CSTR + p4 - 1] : 0.f;
    float cpn = (l < NL - 1 && p4 + 4 < NP) ? cb[(size_t)(l + 1) * CSTR + p4 + 4] : 0.f;
    float cpy = (p4 + 1 < NP) ? cp.y : 0.f;
    float cpz = (p4 + 2 < NP) ? cp.z : 0.f;
    float cpw = (p4 + 3 < NP) ? cp.w : 0.f;
    float4 w;
    w.x = cmw  + cc.x + cpy;
    w.y = cm.x + cc.y + cpz;
    w.z = cm.y + cc.z + cpw;
    w.w = cm.z + cc.w + cpn;
    *(float4*)(g_w + (size_t)bb * NL * CSTR + (size_t)l * CSTR + p4) = w;
}

// -------- launch 5: fuse + mask + softmax (smem mmk cache, unrolled) --------
__global__ __launch_bounds__(256) void k_fuse(float* __restrict__ out) {
    int bb = blockIdx.y;
    int p0 = blockIdx.x * 32;
    int tid = threadIdx.x;
    int w = tid >> 5, lane = tid & 31;
    int p = p0 + lane;
    bool vp = p < NP;
    int pp = vp ? p : 0;

    __shared__ float s_mmk[NL];
#pragma unroll
    for (int i = 0; i < 4; i++) s_mmk[tid + i * 256] = g_mmk[bb * NL + tid + i * 256];

    int y = pp / HS, x = pp - y * HS;
    int m2 = x * HS + y;
    int mpr[3]; bool mval[3];
#pragma unroll
    for (int d = 0; d < 3; d++) {
        int m2d = m2 + d - 1;
        mval[d] = (m2d >= 0 && m2d < NP);
        int mm2 = mval[d] ? m2d : 0;
        int xp2 = mm2 / HS, yp2 = mm2 - xp2 * HS;
        mpr[d] = yp2 * HS + xp2;
    }

    const float* wb = g_w + (size_t)bb * NL * CSTR;
    float mmpv = g_mmp[bb * NP + pp];
    __syncthreads();

    int lbeg = w * 128, lend = lbeg + 128;
    float mx = -INFINITY, s = 0.f;
    float* ob = out + (size_t)bb * NL * NP + pp;
#pragma unroll 4
    for (int l = lbeg; l < lend; l++) {
        int lh = l >> 5, lw = l & 31;
        int n2 = lw * 32 + lh;
        float fs = 0.f;
#pragma unroll
        for (int d2 = 0; d2 < 3; d2++) {
            int n2d = n2 + d2 - 1;
            if ((unsigned)n2d < 1024u && mval[d2]) {
                int np = ((n2d & 31) << 5) | (n2d >> 5);
                fs += wb[(size_t)np * CSTR + mpr[d2]];
            }
        }
        float mmkv = s_mmk[l];
        float mmf = (((mmkv > mmpv) && (mmpv > 0.5f)) || (mmkv == 1.0f)) ? 1.f : 0.f;
        float v = fs * mmf * 10.0f;
        if (vp) ob[(size_t)l * NP] = v;
        float mn = fmaxf(mx, v);
        s = s * __expf(mx - mn) + __expf(v - mn);
        mx = mn;
    }

    __shared__ float smM[8][32], smS[8][32];
    __shared__ float fM[32], fIS[32];
    smM[w][lane] = mx; smS[w][lane] = s;
    __syncthreads();
    if (tid < 32) {
        float M = -INFINITY;
#pragma unroll
        for (int ww = 0; ww < 8; ww++) M = fmaxf(M, smM[ww][tid]);
        float S = 0.f;
#pragma unroll
        for (int ww = 0; ww < 8; ww++) S += smS[ww][tid] * __expf(smM[ww][tid] - M);
        fM[tid] = M; fIS[tid] = 1.0f / S;
    }
    __syncthreads();
    float M = fM[lane], IS = fIS[lane];

    if (vp) {
#pragma unroll 4
        for (int l = lbeg; l < lend; l++) {
            size_t o = (size_t)l * NP;
            ob[o] = __expf(ob[o] - M) * IS;
        }
    }
}

// -------- launch --------
extern "C" void kernel_launch(void* const* d_in, const int* in_sizes, int n_in,
                              void* d_out, int out_size) {
    const float* f    = (const float*)d_in[0];
    const float* b    = (const float*)d_in[1];
    const float* mask = (const float*)d_in[2];
    float* out = (float*)d_out;

    static int smem_set = 0;
    if (!smem_set) {
        cudaFuncSetAttribute(k_gemm_mma, cudaFuncAttributeMaxDynamicSharedMemorySize, SMEM_TOTAL);
        smem_set = 1;
    }

    k_prep<<<BF_BLKS + NB * NC, 256>>>(f, b);                              // 1
    k_buildAFbf<<<A_BLKS + F_BLKS + MK_BLKS, 256>>>(b, mask);              // 2
    k_gemm_mma<<<dim3(PT, MT, NB), 256, SMEM_TOTAL>>>();                   // 3
    k_diag1<<<(NB * 1024 * NP4 + 255) / 256, 256>>>();                     // 4
    k_fuse<<<dim3((NP + 31) / 32, NB), 256>>>(out);                        // 5
}

// round 15
// speedup vs baseline: 1.5272x; 1.0355x over previous
#include <cuda_runtime.h>
#include <cuda_bf16.h>
#include <cstdint>
#include <cstddef>

// Problem constants
#define NB 4
#define NC 64
#define NL 1024
#define HS 63
#define NP 3969
#define CSTR 3972
#define FPW 68

// GEMM tiling
#define KT 16
#define MT 8
#define PT 32
#define A_TILE_B  (128 * 64 * 2)
#define F_TILE_B  (128 * 64 * 2)
#define STAGE_B   (2 * A_TILE_B + 2 * F_TILE_B)   // 65536
#define NSTG 3
#define SMEM_TOTAL (NSTG * STAGE_B)               // 196608

// -------- scratch globals --------
__device__ float g_inv[NB * NC];
__device__ float g_fpad[(size_t)NB * NC * 66 * FPW];
__device__ float g_cos[(size_t)NB * NL * CSTR];
__device__ float g_w[(size_t)NB * NL * CSTR];
__device__ float g_mmk[NB * NL];
__device__ float g_mmp[NB * NP];
__device__ __align__(128) unsigned char g_Abf[(size_t)NB * KT * MT * 2 * A_TILE_B];
__device__ __align__(128) unsigned char g_Fbf[(size_t)NB * KT * PT * 2 * F_TILE_B];

__device__ __forceinline__ int clampi(int v, int lo, int hi) {
    return v < lo ? lo : (v > hi ? hi : v);
}
__device__ __forceinline__ uint32_t smem_u32(const void* p) {
    uint32_t a;
    asm("{ .reg .u64 t; cvta.to.shared.u64 t, %1; cvt.u32.u64 %0, t; }" : "=r"(a) : "l"(p));
    return a;
}
__device__ __forceinline__ void cp16(uint32_t sdst, const void* gsrc) {
    asm volatile("cp.async.cg.shared.global [%0], [%1], 16;" :: "r"(sdst), "l"(gsrc) : "memory");
}
__device__ __forceinline__ void cp_commit() {
    asm volatile("cp.async.commit_group;" ::: "memory");
}
template <int N>
__device__ __forceinline__ void cp_wait() {
    asm volatile("cp.async.wait_group %0;" :: "n"(N) : "memory");
}
__device__ __forceinline__ void ldm_x4(uint32_t* r, uint32_t addr) {
    asm volatile("ldmatrix.sync.aligned.m8n8.x4.shared.b16 {%0,%1,%2,%3}, [%4];"
                 : "=r"(r[0]), "=r"(r[1]), "=r"(r[2]), "=r"(r[3]) : "r"(addr));
}
__device__ __forceinline__ void mma16816(float* d, const uint32_t* a, uint32_t b0, uint32_t b1) {
    asm volatile(
        "mma.sync.aligned.m16n8k16.row.col.f32.bf16.bf16.f32 "
        "{%0,%1,%2,%3}, {%4,%5,%6,%7}, {%8,%9}, {%0,%1,%2,%3};"
        : "+f"(d[0]), "+f"(d[1]), "+f"(d[2]), "+f"(d[3])
        : "r"(a[0]), "r"(a[1]), "r"(a[2]), "r"(a[3]), "r"(b0), "r"(b1));
}

// -------- edge-padded f --------
__global__ void k_buildF(const float* __restrict__ f) {
    int idx = blockIdx.x * 256 + threadIdx.x;
    if (idx >= NB * NC * 66 * FPW) return;
    int col = idx % FPW;
    int row = (idx / FPW) % 66;
    int bc  = idx / (FPW * 66);
    float v = 0.f;
    if (col < 66) {
        int r = clampi(row - 1, 0, 63), c2 = clampi(col - 1, 0, 63);
        v = f[(size_t)bc * 4096 + r * 64 + c2];
    }
    g_fpad[idx] = v;
}

// -------- per-(b,c) L2 norm --------
__global__ void k_norm(const float* __restrict__ bin) {
    int bc = blockIdx.x;
    const float* p = bin + (size_t)bc * 4096;
    float s = 0.f;
    for (int i = threadIdx.x; i < 4096; i += 256) { float v = p[i]; s += v * v; }
    __shared__ float sm[256];
    sm[threadIdx.x] = s; __syncthreads();
    for (int o = 128; o > 0; o >>= 1) {
        if (threadIdx.x < o) sm[threadIdx.x] += sm[threadIdx.x + o];
        __syncthreads();
    }
    if (threadIdx.x == 0) g_inv[bc] = rsqrtf(sm[0] + 1e-8f);
}

// -------- merged A+F bf16 tile build (pre-swizzled, hi/lo) --------
#define A_BLKS 2048
__global__ void k_buildAFbf(const float* __restrict__ bin) {
    if (blockIdx.x < A_BLKS) {
        int idx = blockIdx.x * 256 + threadIdx.x;
        int kc8 = idx & 7;
        int row = (idx >> 3) & 127;
        int lt  = (idx >> 10) & 7;
        int kt  = (idx >> 13) & 15;
        int b   = idx >> 17;
        int l = lt * 128 + row, lh = l >> 5, lw = l & 31;
        union { __nv_bfloat16 h[8]; uint4 v; } Hi, Lo;
#pragma unroll
        for (int r = 0; r < 8; r++) {
            int k = kt * 64 + kc8 * 8 + r;
            int c = k >> 4, i = (k >> 2) & 3, j = k & 3;
            int rr = clampi(2 * lh + i - 1, 0, 63);
            int cc = clampi(2 * lw + j - 1, 0, 63);
            float v = bin[(((size_t)(b * NC + c)) << 12) + (rr << 6) + cc] * g_inv[b * NC + c];
            __nv_bfloat16 hi = __float2bfloat16(v);
            Hi.h[r] = hi;
            Lo.h[r] = __float2bfloat16(v - __bfloat162float(hi));
        }
        uint32_t cb = row * 128 + kc8 * 16;
        uint32_t sw = cb ^ ((cb >> 3) & 0x70);
        size_t base = ((size_t)((b * KT + kt) * MT + lt)) * (2 * A_TILE_B);
        *(uint4*)(g_Abf + base + sw) = Hi.v;
        *(uint4*)(g_Abf + base + A_TILE_B + sw) = Lo.v;
    } else {
        int idx = (blockIdx.x - A_BLKS) * 256 + threadIdx.x;
        int kc8 = idx & 7;
        int row = (idx >> 3) & 127;
        int pt  = (idx >> 10) & 31;
        int kt  = (idx >> 15) & 15;
        int b   = idx >> 19;
        int p = pt * 128 + row;
        union { __nv_bfloat16 h[8]; uint4 v; } Hi, Lo;
        if (p < NP) {
            int y = p / HS, x = p - y * HS;
#pragma unroll
            for (int r = 0; r < 8; r++) {
                int k = kt * 64 + kc8 * 8 + r;
                int c = k >> 4, i = (k >> 2) & 3, j = k & 3;
                float v = g_fpad[((size_t)(b * NC + c) * 66 + (y + i)) * FPW + (x + j)];
                __nv_bfloat16 hi = __float2bfloat16(v);
                Hi.h[r] = hi;
                Lo.h[r] = __float2bfloat16(v - __bfloat162float(hi));
            }
        } else {
            Hi.v = make_uint4(0, 0, 0, 0);
            Lo.v = make_uint4(0, 0, 0, 0);
        }
        uint32_t cb = row * 128 + kc8 * 16;
        uint32_t sw = cb ^ ((cb >> 3) & 0x70);
        size_t base = ((size_t)((b * KT + kt) * PT + pt)) * (2 * F_TILE_B);
        *(uint4*)(g_Fbf + base + sw) = Hi.v;
        *(uint4*)(g_Fbf + base + F_TILE_B + sw) = Lo.v;
    }
}

// -------- mma.sync GEMM: 256 thr, 8 warps (2Mx4N), warp tile 64x32,
//          3-stage cp.async + ks-level fragment double-buffering --------
__global__ __launch_bounds__(256, 1) void k_gemm_mma() {
    extern __shared__ __align__(1024) unsigned char smem[];
    uint32_t sb = smem_u32(smem);
    int tid = threadIdx.x;
    int wid = tid >> 5, lane = tid & 31;
    int pt = blockIdx.x, lt = blockIdx.y, b = blockIdx.z;

    int warpM = (wid >> 2) * 64;
    int warpN = (wid & 3) * 32;

    int a_row = lane & 15;
    int a_kh  = lane >> 4;
    int b_row = (lane & 7) | (((lane >> 4) & 1) << 3);
    int b_kh  = (lane >> 3) & 1;

    float acc[4][4][4];
#pragma unroll
    for (int mt = 0; mt < 4; mt++)
#pragma unroll
        for (int nt = 0; nt < 4; nt++)
#pragma unroll
            for (int r = 0; r < 4; r++) acc[mt][nt][r] = 0.f;

    const size_t Astride = (size_t)MT * 2 * A_TILE_B;
    const size_t Fstride = (size_t)PT * 2 * F_TILE_B;
    const unsigned char* Ab0 = g_Abf + ((size_t)(b * KT) * MT + lt) * (2 * A_TILE_B);
    const unsigned char* Fb0 = g_Fbf + ((size_t)(b * KT) * PT + pt) * (2 * F_TILE_B);

    auto load_stage = [&](int s, int kt) {
        uint32_t dst = sb + s * STAGE_B;
        const unsigned char* As = Ab0 + (size_t)kt * Astride;
        const unsigned char* Fs = Fb0 + (size_t)kt * Fstride;
#pragma unroll
        for (int i = 0; i < 16; i++) {
            int idx = tid + i * 256;
            const unsigned char* g = (idx < 2048) ? (As + (size_t)idx * 16)
                                                  : (Fs + (size_t)(idx - 2048) * 16);
            cp16(dst + idx * 16, g);
        }
        cp_commit();
    };

    uint32_t ahi[2][4][4], alo[2][4][4], fhi[2][2][4], flo[2][2][4];

    auto load_frags = [&](int buf, uint32_t SA, int ks) {
#pragma unroll
        for (int mt = 0; mt < 4; mt++) {
            int row = warpM + mt * 16 + a_row;
            uint32_t ad = SA + row * 128 + (((ks * 2 + a_kh) ^ (a_row & 7)) << 4);
            ldm_x4(ahi[buf][mt], ad);
            ldm_x4(alo[buf][mt], ad + 16384);
        }
#pragma unroll
        for (int ntp = 0; ntp < 2; ntp++) {
            int row = warpN + ntp * 16 + b_row;
            uint32_t fd = SA + 32768 + row * 128 + (((ks * 2 + b_kh) ^ (b_row & 7)) << 4);
            ldm_x4(fhi[buf][ntp], fd);
            ldm_x4(flo[buf][ntp], fd + 16384);
        }
    };

    load_stage(0, 0);
    load_stage(1, 1);

    for (int kt = 0; kt < KT; kt++) {
        int s = kt % NSTG;
        if (kt + 2 < KT) { load_stage((kt + 2) % NSTG, kt + 2); cp_wait<2>(); }
        else if (kt + 1 < KT) cp_wait<1>();
        else cp_wait<0>();
        __syncthreads();

        uint32_t SA = sb + s * STAGE_B;
        load_frags(0, SA, 0);
#pragma unroll
        for (int ks = 0; ks < 4; ks++) {
            int cur = ks & 1, nxt = cur ^ 1;
            if (ks < 3) load_frags(nxt, SA, ks + 1);
#pragma unroll
            for (int term = 0; term < 3; term++)
#pragma unroll
                for (int mt = 0; mt < 4; mt++)
#pragma unroll
                    for (int nt = 0; nt < 4; nt++) {
                        int ntp = nt >> 1, rb = (nt & 1) * 2;
                        if (term == 0)
                            mma16816(acc[mt][nt], ahi[cur][mt], fhi[cur][ntp][rb], fhi[cur][ntp][rb + 1]);
                        else if (term == 1)
                            mma16816(acc[mt][nt], ahi[cur][mt], flo[cur][ntp][rb], flo[cur][ntp][rb + 1]);
                        else
                            mma16816(acc[mt][nt], alo[cur][mt], fhi[cur][ntp][rb], fhi[cur][ntp][rb + 1]);
                    }
        }
        __syncthreads();
    }

    // epilogue (CSTR stride)
    int lrow = lt * 128 + warpM + (lane >> 2);
    int pcol = pt * 128 + warpN + (lane & 3) * 2;
#pragma unroll
    for (int mt = 0; mt < 4; mt++) {
        int l0 = lrow + mt * 16;
        float* C0 = g_cos + ((size_t)(b * NL + l0)) * CSTR;
        float* C8 = C0 + (size_t)8 * CSTR;
#pragma unroll
        for (int nt = 0; nt < 4; nt++) {
            int p = pcol + nt * 8;
            if (p < NP)     { C0[p]     = acc[mt][nt][0]; C8[p]     = acc[mt][nt][2]; }
            if (p + 1 < NP) { C0[p + 1] = acc[mt][nt][1]; C8[p + 1] = acc[mt][nt][3]; }
        }
    }
}

// -------- first diagonal pass (vectorized, CSTR) --------
#define NP4 993
__global__ __launch_bounds__(256) void k_diag1() {
    int gp = blockIdx.x * 256 + threadIdx.x;
    int v4 = gp % NP4;
    int l  = (gp / NP4) & 1023;
    int bb = gp / (NP4 * 1024);
    if (bb >= NB) return;
    int p4 = v4 * 4;
    const float* cb = g_cos + (size_t)bb * NL * CSTR;
    const float4 z4 = make_float4(0.f, 0.f, 0.f, 0.f);
    float4 cm = (l > 0)      ? *(const float4*)(cb + (size_t)(l - 1) * CSTR + p4) : z4;
    float4 cc =                *(const float4*)(cb + (size_t)l * CSTR + p4);
    float4 cp = (l < NL - 1) ? *(const float4*)(cb + (size_t)(l + 1) * CSTR + p4) : z4;
    float cmw = (l > 0 && p4 > 0) ? cb[(size_t)(l - 1) * CSTR + p4 - 1] : 0.f;
    float cpn = (l < NL - 1 && p4 + 4 < NP) ? cb[(size_t)(l + 1) * CSTR + p4 + 4] : 0.f;
    float cpy = (p4 + 1 < NP) ? cp.y : 0.f;
    float cpz = (p4 + 2 < NP) ? cp.z : 0.f;
    float cpw = (p4 + 3 < NP) ? cp.w : 0.f;
    float4 w;
    w.x = cmw  + cc.x + cpy;
    w.y = cm.x + cc.y + cpz;
    w.z = cm.y + cc.z + cpw;
    w.w = cm.z + cc.w + cpn;
    *(float4*)(g_w + (size_t)bb * NL * CSTR + (size_t)l * CSTR + p4) = w;
}

// -------- mask means (merged) --------
__global__ void k_masks(const float* __restrict__ mask) {
    int idx = blockIdx.x * 256 + threadIdx.x;
    if (idx < NB * NL) {
        int bb = idx >> 10, l = idx & 1023;
        int lh = l >> 5, lw = l & 31;
        float s = 0.f;
        for (int i = 0; i < 4; i++)
            for (int j = 0; j < 4; j++) {
                int r  = clampi(2 * lh + i - 1, 0, 63);
                int cc = clampi(2 * lw + j - 1, 0, 63);
                s += 1.0f - mask[bb * 4096 + r * 64 + cc];
            }
        g_mmk[idx] = s * 0.0625f;
    } else {
        int id2 = idx - NB * NL;
        if (id2 >= NB * NP) return;
        int bb = id2 / NP;
        int p  = id2 - bb * NP;
        int y  = p / HS, x = p - y * HS;
        float s = 0.f;
        for (int i = 0; i < 4; i++)
            for (int j = 0; j < 4; j++) {
                int r  = clampi(y + i - 1, 0, 63);
                int cc = clampi(x + j - 1, 0, 63);
                s += 1.0f - mask[bb * 4096 + r * 64 + cc];
            }
        g_mmp[id2] = s * 0.0625f;
    }
}

// -------- single-kernel fuse + softmax (R11 + smem mmk cache only) --------
__global__ __launch_bounds__(256) void k_fuse(float* __restrict__ out) {
    int bb = blockIdx.y;
    int p0 = blockIdx.x * 32;
    int tid = threadIdx.x;
    int w = tid >> 5, lane = tid & 31;
    int p = p0 + lane;
    bool vp = p < NP;
    int pp = vp ? p : 0;

    __shared__ float s_mmk[NL];
#pragma unroll
    for (int i = 0; i < 4; i++) s_mmk[tid + i * 256] = g_mmk[bb * NL + tid + i * 256];

    int y = pp / HS, x = pp - y * HS;
    int m2 = x * HS + y;
    int mpr[3]; bool mval[3];
#pragma unroll
    for (int d = 0; d < 3; d++) {
        int m2d = m2 + d - 1;
        mval[d] = (m2d >= 0 && m2d < NP);
        int mm2 = mval[d] ? m2d : 0;
        int xp2 = mm2 / HS, yp2 = mm2 - xp2 * HS;
        mpr[d] = yp2 * HS + xp2;
    }

    const float* wb = g_w + (size_t)bb * NL * CSTR;
    float mmpv = g_mmp[bb * NP + pp];
    __syncthreads();

    int lbeg = w * 128, lend = lbeg + 128;
    float mx = -INFINITY, s = 0.f;
    float* ob = out + (size_t)bb * NL * NP + pp;
    for (int l = lbeg; l < lend; l++) {
        int lh = l >> 5, lw = l & 31;
        int n2 = lw * 32 + lh;
        float fs = 0.f;
#pragma unroll
        for (int d2 = 0; d2 < 3; d2++) {
            int n2d = n2 + d2 - 1;
            if ((unsigned)n2d < 1024u && mval[d2]) {
                int np = ((n2d & 31) << 5) | (n2d >> 5);
                fs += wb[(size_t)np * CSTR + mpr[d2]];
            }
        }
        float mmkv = s_mmk[l];
        float mmf = (((mmkv > mmpv) && (mmpv > 0.5f)) || (mmkv == 1.0f)) ? 1.f : 0.f;
        float v = fs * mmf * 10.0f;
        if (vp) ob[(size_t)l * NP] = v;
        float mn = fmaxf(mx, v);
        s = s * __expf(mx - mn) + __expf(v - mn);
        mx = mn;
    }

    __shared__ float smM[8][32], smS[8][32];
    __shared__ float fM[32], fIS[32];
    smM[w][lane] = mx; smS[w][lane] = s;
    __syncthreads();
    if (tid < 32) {
        float M = -INFINITY;
#pragma unroll
        for (int ww = 0; ww < 8; ww++) M = fmaxf(M, smM[ww][tid]);
        float S = 0.f;
#pragma unroll
        for (int ww = 0; ww < 8; ww++) S += smS[ww][tid] * __expf(smM[ww][tid] - M);
        fM[tid] = M; fIS[tid] = 1.0f / S;
    }
    __syncthreads();
    float M = fM[lane], IS = fIS[lane];

    if (vp)
        for (int l = lbeg; l < lend; l++) {
            size_t o = (size_t)l * NP;
            ob[o] = __expf(ob[o] - M) * IS;
        }
}

// -------- launch --------
extern "C" void kernel_launch(void* const* d_in, const int* in_sizes, int n_in,
                              void* d_out, int out_size) {
    const float* f    = (const float*)d_in[0];
    const float* b    = (const float*)d_in[1];
    const float* mask = (const float*)d_in[2];
    float* out = (float*)d_out;

    static int smem_set = 0;
    if (!smem_set) {
        cudaFuncSetAttribute(k_gemm_mma, cudaFuncAttributeMaxDynamicSharedMemorySize, SMEM_TOTAL);
        smem_set = 1;
    }

    k_buildF<<<(NB * NC * 66 * FPW + 255) / 256, 256>>>(f);                // 1
    k_norm<<<NB * NC, 256>>>(b);                                           // 2
    k_buildAFbf<<<A_BLKS + 8192, 256>>>(b);                                // 3
    k_gemm_mma<<<dim3(PT, MT, NB), 256, SMEM_TOTAL>>>();                   // 4  <- ncu window
    k_diag1<<<(NB * 1024 * NP4 + 255) / 256, 256>>>();                     // 5
    k_masks<<<(NB * NL + NB * NP + 255) / 256, 256>>>(mask);               // 6
    k_fuse<<<dim3((NP + 31) / 32, NB), 256>>>(out);                        // 7
}

// round 16
// speedup vs baseline: 1.6764x; 1.0977x over previous
#include <cuda_runtime.h>
#include <cuda_bf16.h>
#include <cstdint>
#include <cstddef>

// Problem constants
#define NB 4
#define NC 64
#define NL 1024
#define HS 63
#define NP 3969
#define CSTR 3972
#define FPW 68

// GEMM tiling: CTA 64x128, 4 warps (1M x 4N), warp tile 64x32, 2 CTAs/SM
#define KT 16
#define MT 8           // A build tiling (128-row tiles) unchanged
#define MT2 16         // GEMM M-blocks of 64
#define PT 32
#define A_TILE_B  (128 * 64 * 2)      // built A tile (128 rows)
#define F_TILE_B  (128 * 64 * 2)
#define STAGE_B   49152               // Ahi 8K + Alo 8K + Fhi 16K + Flo 16K
#define NSTG 2
#define SMEM_TOTAL (NSTG * STAGE_B)   // 98304 -> 2 CTAs/SM

// -------- scratch globals --------
__device__ float g_inv[NB * NC];
__device__ float g_fpad[(size_t)NB * NC * 66 * FPW];
__device__ float g_cos[(size_t)NB * NL * CSTR];
__device__ float g_w[(size_t)NB * NL * CSTR];
__device__ float g_mmk[NB * NL];
__device__ float g_mmp[NB * NP];
__device__ __align__(128) unsigned char g_Abf[(size_t)NB * KT * MT * 2 * A_TILE_B];
__device__ __align__(128) unsigned char g_Fbf[(size_t)NB * KT * PT * 2 * F_TILE_B];

__device__ __forceinline__ int clampi(int v, int lo, int hi) {
    return v < lo ? lo : (v > hi ? hi : v);
}
__device__ __forceinline__ uint32_t smem_u32(const void* p) {
    uint32_t a;
    asm("{ .reg .u64 t; cvta.to.shared.u64 t, %1; cvt.u32.u64 %0, t; }" : "=r"(a) : "l"(p));
    return a;
}
__device__ __forceinline__ void cp16(uint32_t sdst, const void* gsrc) {
    asm volatile("cp.async.cg.shared.global [%0], [%1], 16;" :: "r"(sdst), "l"(gsrc) : "memory");
}
__device__ __forceinline__ void cp_commit() {
    asm volatile("cp.async.commit_group;" ::: "memory");
}
template <int N>
__device__ __forceinline__ void cp_wait() {
    asm volatile("cp.async.wait_group %0;" :: "n"(N) : "memory");
}
__device__ __forceinline__ void ldm_x4(uint32_t* r, uint32_t addr) {
    asm volatile("ldmatrix.sync.aligned.m8n8.x4.shared.b16 {%0,%1,%2,%3}, [%4];"
                 : "=r"(r[0]), "=r"(r[1]), "=r"(r[2]), "=r"(r[3]) : "r"(addr));
}
__device__ __forceinline__ void mma16816(float* d, const uint32_t* a, uint32_t b0, uint32_t b1) {
    asm volatile(
        "mma.sync.aligned.m16n8k16.row.col.f32.bf16.bf16.f32 "
        "{%0,%1,%2,%3}, {%4,%5,%6,%7}, {%8,%9}, {%0,%1,%2,%3};"
        : "+f"(d[0]), "+f"(d[1]), "+f"(d[2]), "+f"(d[3])
        : "r"(a[0]), "r"(a[1]), "r"(a[2]), "r"(a[3]), "r"(b0), "r"(b1));
}

// -------- edge-padded f --------
__global__ void k_buildF(const float* __restrict__ f) {
    int idx = blockIdx.x * 256 + threadIdx.x;
    if (idx >= NB * NC * 66 * FPW) return;
    int col = idx % FPW;
    int row = (idx / FPW) % 66;
    int bc  = idx / (FPW * 66);
    float v = 0.f;
    if (col < 66) {
        int r = clampi(row - 1, 0, 63), c2 = clampi(col - 1, 0, 63);
        v = f[(size_t)bc * 4096 + r * 64 + c2];
    }
    g_fpad[idx] = v;
}

// -------- per-(b,c) L2 norm --------
__global__ void k_norm(const float* __restrict__ bin) {
    int bc = blockIdx.x;
    const float* p = bin + (size_t)bc * 4096;
    float s = 0.f;
    for (int i = threadIdx.x; i < 4096; i += 256) { float v = p[i]; s += v * v; }
    __shared__ float sm[256];
    sm[threadIdx.x] = s; __syncthreads();
    for (int o = 128; o > 0; o >>= 1) {
        if (threadIdx.x < o) sm[threadIdx.x] += sm[threadIdx.x + o];
        __syncthreads();
    }
    if (threadIdx.x == 0) g_inv[bc] = rsqrtf(sm[0] + 1e-8f);
}

// -------- merged A+F bf16 tile build (pre-swizzled, hi/lo) --------
#define A_BLKS 2048
__global__ void k_buildAFbf(const float* __restrict__ bin) {
    if (blockIdx.x < A_BLKS) {
        int idx = blockIdx.x * 256 + threadIdx.x;
        int kc8 = idx & 7;
        int row = (idx >> 3) & 127;
        int lt  = (idx >> 10) & 7;
        int kt  = (idx >> 13) & 15;
        int b   = idx >> 17;
        int l = lt * 128 + row, lh = l >> 5, lw = l & 31;
        union { __nv_bfloat16 h[8]; uint4 v; } Hi, Lo;
#pragma unroll
        for (int r = 0; r < 8; r++) {
            int k = kt * 64 + kc8 * 8 + r;
            int c = k >> 4, i = (k >> 2) & 3, j = k & 3;
            int rr = clampi(2 * lh + i - 1, 0, 63);
            int cc = clampi(2 * lw + j - 1, 0, 63);
            float v = bin[(((size_t)(b * NC + c)) << 12) + (rr << 6) + cc] * g_inv[b * NC + c];
            __nv_bfloat16 hi = __float2bfloat16(v);
            Hi.h[r] = hi;
            Lo.h[r] = __float2bfloat16(v - __bfloat162float(hi));
        }
        uint32_t cb = row * 128 + kc8 * 16;
        uint32_t sw = cb ^ ((cb >> 3) & 0x70);
        size_t base = ((size_t)((b * KT + kt) * MT + lt)) * (2 * A_TILE_B);
        *(uint4*)(g_Abf + base + sw) = Hi.v;
        *(uint4*)(g_Abf + base + A_TILE_B + sw) = Lo.v;
    } else {
        int idx = (blockIdx.x - A_BLKS) * 256 + threadIdx.x;
        int kc8 = idx & 7;
        int row = (idx >> 3) & 127;
        int pt  = (idx >> 10) & 31;
        int kt  = (idx >> 15) & 15;
        int b   = idx >> 19;
        int p = pt * 128 + row;
        union { __nv_bfloat16 h[8]; uint4 v; } Hi, Lo;
        if (p < NP) {
            int y = p / HS, x = p - y * HS;
#pragma unroll
            for (int r = 0; r < 8; r++) {
                int k = kt * 64 + kc8 * 8 + r;
                int c = k >> 4, i = (k >> 2) & 3, j = k & 3;
                float v = g_fpad[((size_t)(b * NC + c) * 66 + (y + i)) * FPW + (x + j)];
                __nv_bfloat16 hi = __float2bfloat16(v);
                Hi.h[r] = hi;
                Lo.h[r] = __float2bfloat16(v - __bfloat162float(hi));
            }
        } else {
            Hi.v = make_uint4(0, 0, 0, 0);
            Lo.v = make_uint4(0, 0, 0, 0);
        }
        uint32_t cb = row * 128 + kc8 * 16;
        uint32_t sw = cb ^ ((cb >> 3) & 0x70);
        size_t base = ((size_t)((b * KT + kt) * PT + pt)) * (2 * F_TILE_B);
        *(uint4*)(g_Fbf + base + sw) = Hi.v;
        *(uint4*)(g_Fbf + base + F_TILE_B + sw) = Lo.v;
    }
}

// -------- mma.sync GEMM: CTA 64x128, 128 thr, 4 warps (1Mx4N), warp 64x32,
//          2-stage cp.async, fragment double-buffer, 2 CTAs/SM --------
__global__ __launch_bounds__(128, 2) void k_gemm_mma() {
    extern __shared__ __align__(1024) unsigned char smem[];
    uint32_t sb = smem_u32(smem);
    int tid = threadIdx.x;
    int wid = tid >> 5, lane = tid & 31;
    int pt = blockIdx.x, lt2 = blockIdx.y, b = blockIdx.z;
    int lt = lt2 >> 1, half = lt2 & 1;

    int warpN = wid * 32;

    int a_row = lane & 15;
    int a_kh  = lane >> 4;
    int b_row = (lane & 7) | (((lane >> 4) & 1) << 3);
    int b_kh  = (lane >> 3) & 1;

    float acc[4][4][4];
#pragma unroll
    for (int mt = 0; mt < 4; mt++)
#pragma unroll
        for (int nt = 0; nt < 4; nt++)
#pragma unroll
            for (int r = 0; r < 4; r++) acc[mt][nt][r] = 0.f;

    const size_t Astride = (size_t)MT * 2 * A_TILE_B;
    const size_t Fstride = (size_t)PT * 2 * F_TILE_B;
    // A: 64-row half of the built 128-row tile (hi at +half*8192, lo at +16384+half*8192)
    const unsigned char* Ab0 = g_Abf + ((size_t)(b * KT) * MT + lt) * (2 * A_TILE_B) + half * 8192;
    const unsigned char* Fb0 = g_Fbf + ((size_t)(b * KT) * PT + pt) * (2 * F_TILE_B);

    auto load_stage = [&](int s, int kt) {
        uint32_t dst = sb + s * STAGE_B;
        const unsigned char* Ahi = Ab0 + (size_t)kt * Astride;
        const unsigned char* Alo = Ahi + 16384;
        const unsigned char* Fs  = Fb0 + (size_t)kt * Fstride;
#pragma unroll
        for (int i = 0; i < 24; i++) {
            int idx = tid + i * 128;                  // 0..3071 chunks of 16B
            const unsigned char* g;
            if (idx < 512)        g = Ahi + (size_t)idx * 16;
            else if (idx < 1024)  g = Alo + (size_t)(idx - 512) * 16;
            else                  g = Fs  + (size_t)(idx - 1024) * 16;
            cp16(dst + idx * 16, g);
        }
        cp_commit();
    };

    // smem stage layout: Ahi @0 (8K), Alo @8192, Fhi @16384 (16K), Flo @32768
    uint32_t ahi[2][4][4], alo[2][4][4], fhi[2][2][4], flo[2][2][4];

    auto load_frags = [&](int buf, uint32_t SA, int ks) {
#pragma unroll
        for (int mt = 0; mt < 4; mt++) {
            int row = mt * 16 + a_row;                // 0..63
            uint32_t ad = SA + row * 128 + (((ks * 2 + a_kh) ^ (a_row & 7)) << 4);
            ldm_x4(ahi[buf][mt], ad);
            ldm_x4(alo[buf][mt], ad + 8192);
        }
#pragma unroll
        for (int ntp = 0; ntp < 2; ntp++) {
            int row = warpN + ntp * 16 + b_row;
            uint32_t fd = SA + 16384 + row * 128 + (((ks * 2 + b_kh) ^ (b_row & 7)) << 4);
            ldm_x4(fhi[buf][ntp], fd);
            ldm_x4(flo[buf][ntp], fd + 16384);
        }
    };

    load_stage(0, 0);

    for (int kt = 0; kt < KT; kt++) {
        int s = kt & 1;
        if (kt + 1 < KT) { load_stage(s ^ 1, kt + 1); cp_wait<1>(); }
        else             { cp_wait<0>(); }
        __syncthreads();

        uint32_t SA = sb + s * STAGE_B;
        load_frags(0, SA, 0);
#pragma unroll
        for (int ks = 0; ks < 4; ks++) {
            int cur = ks & 1, nxt = cur ^ 1;
            if (ks < 3) load_frags(nxt, SA, ks + 1);
#pragma unroll
            for (int term = 0; term < 3; term++)
#pragma unroll
                for (int mt = 0; mt < 4; mt++)
#pragma unroll
                    for (int nt = 0; nt < 4; nt++) {
                        int ntp = nt >> 1, rb = (nt & 1) * 2;
                        if (term == 0)
                            mma16816(acc[mt][nt], ahi[cur][mt], fhi[cur][ntp][rb], fhi[cur][ntp][rb + 1]);
                        else if (term == 1)
                            mma16816(acc[mt][nt], ahi[cur][mt], flo[cur][ntp][rb], flo[cur][ntp][rb + 1]);
                        else
                            mma16816(acc[mt][nt], alo[cur][mt], fhi[cur][ntp][rb], fhi[cur][ntp][rb + 1]);
                    }
        }
        __syncthreads();
    }

    // epilogue (CSTR stride)
    int lrow = lt2 * 64 + (lane >> 2);
    int pcol = pt * 128 + warpN + (lane & 3) * 2;
#pragma unroll
    for (int mt = 0; mt < 4; mt++) {
        int l0 = lrow + mt * 16;
        float* C0 = g_cos + ((size_t)(b * NL + l0)) * CSTR;
        float* C8 = C0 + (size_t)8 * CSTR;
#pragma unroll
        for (int nt = 0; nt < 4; nt++) {
            int p = pcol + nt * 8;
            if (p < NP)     { C0[p]     = acc[mt][nt][0]; C8[p]     = acc[mt][nt][2]; }
            if (p + 1 < NP) { C0[p + 1] = acc[mt][nt][1]; C8[p + 1] = acc[mt][nt][3]; }
        }
    }
}

// -------- first diagonal pass (vectorized, CSTR) --------
#define NP4 993
__global__ __launch_bounds__(256) void k_diag1() {
    int gp = blockIdx.x * 256 + threadIdx.x;
    int v4 = gp % NP4;
    int l  = (gp / NP4) & 1023;
    int bb = gp / (NP4 * 1024);
    if (bb >= NB) return;
    int p4 = v4 * 4;
    const float* cb = g_cos + (size_t)bb * NL * CSTR;
    const float4 z4 = make_float4(0.f, 0.f, 0.f, 0.f);
    float4 cm = (l > 0)      ? *(const float4*)(cb + (size_t)(l - 1) * CSTR + p4) : z4;
    float4 cc =                *(const float4*)(cb + (size_t)l * CSTR + p4);
    float4 cp = (l < NL - 1) ? *(const float4*)(cb + (size_t)(l + 1) * CSTR + p4) : z4;
    float cmw = (l > 0 && p4 > 0) ? cb[(size_t)(l - 1) * CSTR + p4 - 1] : 0.f;
    float cpn = (l < NL - 1 && p4 + 4 < NP) ? cb[(size_t)(l + 1) * CSTR + p4 + 4] : 0.f;
    float cpy = (p4 + 1 < NP) ? cp.y : 0.f;
    float cpz = (p4 + 2 < NP) ? cp.z : 0.f;
    float cpw = (p4 + 3 < NP) ? cp.w : 0.f;
    float4 w;
    w.x = cmw  + cc.x + cpy;
    w.y = cm.x + cc.y + cpz;
    w.z = cm.y + cc.z + cpw;
    w.w = cm.z + cc.w + cpn;
    *(float4*)(g_w + (size_t)bb * NL * CSTR + (size_t)l * CSTR + p4) = w;
}

// -------- mask means (merged) --------
__global__ void k_masks(const float* __restrict__ mask) {
    int idx = blockIdx.x * 256 + threadIdx.x;
    if (idx < NB * NL) {
        int bb = idx >> 10, l = idx & 1023;
        int lh = l >> 5, lw = l & 31;
        float s = 0.f;
        for (int i = 0; i < 4; i++)
            for (int j = 0; j < 4; j++) {
                int r  = clampi(2 * lh + i - 1, 0, 63);
                int cc = clampi(2 * lw + j - 1, 0, 63);
                s += 1.0f - mask[bb * 4096 + r * 64 + cc];
            }
        g_mmk[idx] = s * 0.0625f;
    } else {
        int id2 = idx - NB * NL;
        if (id2 >= NB * NP) return;
        int bb = id2 / NP;
        int p  = id2 - bb * NP;
        int y  = p / HS, x = p - y * HS;
        float s = 0.f;
        for (int i = 0; i < 4; i++)
            for (int j = 0; j < 4; j++) {
                int r  = clampi(y + i - 1, 0, 63);
                int cc = clampi(x + j - 1, 0, 63);
                s += 1.0f - mask[bb * 4096 + r * 64 + cc];
            }
        g_mmp[id2] = s * 0.0625f;
    }
}

// -------- fused value: 3-point gather on w (exact R11) --------
__device__ __forceinline__ float fused_val(const float* __restrict__ wb, int bb, int l,
                                           const int mpr[3], const bool mval[3],
                                           float mmpv) {
    int lh = l >> 5, lw = l & 31;
    int n2 = lw * 32 + lh;
    float fs = 0.f;
#pragma unroll
    for (int d2 = 0; d2 < 3; d2++) {
        int n2d = n2 + d2 - 1;
        if ((unsigned)n2d < 1024u && mval[d2]) {
            int np = ((n2d & 31) << 5) | (n2d >> 5);
            fs += wb[(size_t)np * CSTR + mpr[d2]];
        }
    }
    float mmkv = g_mmk[bb * NL + l];
    float mmf = (((mmkv > mmpv) && (mmpv > 0.5f)) || (mmkv == 1.0f)) ? 1.f : 0.f;
    return fs * mmf * 10.0f;
}

// -------- single-kernel fuse + softmax (exact R11) --------
__global__ __launch_bounds__(256) void k_fuse(float* __restrict__ out) {
    int bb = blockIdx.y;
    int p0 = blockIdx.x * 32;
    int tid = threadIdx.x;
    int w = tid >> 5, lane = tid & 31;
    int p = p0 + lane;
    bool vp = p < NP;
    int pp = vp ? p : 0;

    int y = pp / HS, x = pp - y * HS;
    int m2 = x * HS + y;
    int mpr[3]; bool mval[3];
#pragma unroll
    for (int d = 0; d < 3; d++) {
        int m2d = m2 + d - 1;
        mval[d] = (m2d >= 0 && m2d < NP);
        int mm2 = mval[d] ? m2d : 0;
        int xp2 = mm2 / HS, yp2 = mm2 - xp2 * HS;
        mpr[d] = yp2 * HS + xp2;
    }

    const float* wb = g_w + (size_t)bb * NL * CSTR;
    float mmpv = g_mmp[bb * NP + pp];

    int lbeg = w * 128, lend = lbeg + 128;
    float mx = -INFINITY, s = 0.f;
    float* ob = out + (size_t)bb * NL * NP + pp;
    for (int l = lbeg; l < lend; l++) {
        float v = fused_val(wb, bb, l, mpr, mval, mmpv);
        if (vp) ob[(size_t)l * NP] = v;
        float mn = fmaxf(mx, v);
        s = s * __expf(mx - mn) + __expf(v - mn);
        mx = mn;
    }

    __shared__ float smM[8][32], smS[8][32];
    __shared__ float fM[32], fIS[32];
    smM[w][lane] = mx; smS[w][lane] = s;
    __syncthreads();
    if (tid < 32) {
        float M = -INFINITY;
#pragma unroll
        for (int ww = 0; ww < 8; ww++) M = fmaxf(M, smM[ww][tid]);
        float S = 0.f;
#pragma unroll
        for (int ww = 0; ww < 8; ww++) S += smS[ww][tid] * __expf(smM[ww][tid] - M);
        fM[tid] = M; fIS[tid] = 1.0f / S;
    }
    __syncthreads();
    float M = fM[lane], IS = fIS[lane];

    if (vp)
        for (int l = lbeg; l < lend; l++) {
            size_t o = (size_t)l * NP;
            ob[o] = __expf(ob[o] - M) * IS;
        }
}

// -------- launch --------
extern "C" void kernel_launch(void* const* d_in, const int* in_sizes, int n_in,
                              void* d_out, int out_size) {
    const float* f    = (const float*)d_in[0];
    const float* b    = (const float*)d_in[1];
    const float* mask = (const float*)d_in[2];
    float* out = (float*)d_out;

    static int smem_set = 0;
    if (!smem_set) {
        cudaFuncSetAttribute(k_gemm_mma, cudaFuncAttributeMaxDynamicSharedMemorySize, SMEM_TOTAL);
        smem_set = 1;
    }

    k_buildF<<<(NB * NC * 66 * FPW + 255) / 256, 256>>>(f);                // 1
    k_norm<<<NB * NC, 256>>>(b);                                           // 2
    k_buildAFbf<<<A_BLKS + 8192, 256>>>(b);                                // 3
    k_gemm_mma<<<dim3(PT, MT2, NB), 128, SMEM_TOTAL>>>();                  // 4  <- ncu window
    k_diag1<<<(NB * 1024 * NP4 + 255) / 256, 256>>>();                     // 5
    k_masks<<<(NB * NL + NB * NP + 255) / 256, 256>>>(mask);               // 6
    k_fuse<<<dim3((NP + 31) / 32, NB), 256>>>(out);                        // 7
}